// round 16
// baseline (speedup 1.0000x reference)
#include <cuda_runtime.h>
#include <cuda_bf16.h>
#include <math.h>

#define Bb   4
#define Nn   2048
#define Ss   256
#define Cc   64
#define Hh   4
#define Dd   64
#define Ff   1024
#define ROWS (Bb*Nn)          // 8192

// ---------------- scratch (static device memory; no allocations) -------------
__device__ float g_sn[ROWS*Ss];
__device__ float g_vn[ROWS*Cc*3];
__device__ float g_q[ROWS*Ss];
__device__ float g_k[ROWS*Ss];
__device__ float g_vp[ROWS*Ss];
__device__ float g_vmix[ROWS*Cc*3];
__device__ __nv_bfloat16 g_probs[(size_t)Bb*Hh*Nn*Nn];   // 134 MB unnormalized probs
__device__ float g_linv[(size_t)Bb*Hh*Nn];
__device__ float g_sattn[ROWS*Ss];
__device__ float g_vattn[ROWS*Cc*3];
__device__ float g_ffn[ROWS*Ff];

// ---------------- cp.async helpers -------------------------------------------
__device__ __forceinline__ void cp16(void* s, const void* g) {
    unsigned sa = (unsigned)__cvta_generic_to_shared(s);
    asm volatile("cp.async.cg.shared.global [%0], [%1], 16;\n" :: "r"(sa), "l"(g) : "memory");
}
#define CP_COMMIT() asm volatile("cp.async.commit_group;\n" ::: "memory")
#define CP_WAIT0()  asm volatile("cp.async.wait_group 0;\n" ::: "memory")
#define CP_WAIT1()  asm volatile("cp.async.wait_group 1;\n" ::: "memory")

// ---------------- eq layernorm (+ optional fused vmix) -----------------------
__global__ void __launch_bounds__(256) eqln_kernel(
    const float* __restrict__ sin, const float* __restrict__ vin,
    const float* __restrict__ g, const float* __restrict__ be,
    const float* __restrict__ vsc,
    float* __restrict__ sn, float* __restrict__ vn,
    const float* __restrict__ Wvv, float* __restrict__ vmixO)
{
    long long row = blockIdx.x;
    int tid = threadIdx.x;
    __shared__ float redA[8], redB[8], norms[64], st[3], vsh[192];

    float x = sin[row*Ss + tid];
    float s1 = x, s2 = x*x;
    #pragma unroll
    for (int o = 16; o; o >>= 1) {
        s1 += __shfl_xor_sync(0xffffffffu, s1, o);
        s2 += __shfl_xor_sync(0xffffffffu, s2, o);
    }
    if ((tid & 31) == 0) { redA[tid>>5] = s1; redB[tid>>5] = s2; }

    if (tid < 64) {
        const float* vp = vin + row*192 + tid*3;
        float a = vp[0], b2 = vp[1], c = vp[2];
        norms[tid] = sqrtf(a*a + b2*b2 + c*c);
    }
    __syncthreads();
    if (tid == 0) {
        float A = 0.f, Bs2 = 0.f;
        #pragma unroll
        for (int w = 0; w < 8; w++) { A += redA[w]; Bs2 += redB[w]; }
        float mu  = A * (1.f/256.f);
        float var = Bs2 * (1.f/256.f) - mu*mu;
        st[0] = mu; st[1] = rsqrtf(var + 1e-5f);
        float t = 0.f;
        for (int c = 0; c < 64; c++) t += norms[c];
        st[2] = t * (1.f/64.f);
    }
    __syncthreads();
    sn[row*Ss + tid] = (x - st[0]) * st[1] * g[tid] + be[tid];
    if (tid < 192) {
        int c = tid / 3;
        float val = vin[row*192 + tid] / (norms[c] + 1e-5f) * st[2] * vsc[c];
        vn[row*192 + tid] = val;
        vsh[tid] = val;
    }
    if (vmixO) {
        __syncthreads();
        if (tid < 192) {
            int xx = tid >> 6, e = tid & 63;
            float acc = 0.f;
            #pragma unroll 8
            for (int c = 0; c < 64; c++) acc += vsh[c*3 + xx] * Wvv[c*64 + e];
            vmixO[row*192 + e*3 + xx] = acc;
        }
    }
}

// ---------------- bf16 tensor-core GEMM: 128x64 CTA, mma.m16n8k16 ------------
#define TCK 32
#define AS2_LD 132          // [16 pairs][128 m + pad] uints
#define BS2_LD 68           // [16 pairs][64 n + pad] uints
#define GEMM_TC_SMEM ((2*16*AS2_LD + 2*16*BS2_LD)*4)

__device__ __forceinline__ unsigned pkbf(float x, float y) {
    __nv_bfloat162 h = __floats2bfloat162_rn(x, y);
    return *(unsigned*)&h;
}

__device__ __forceinline__ void mma_bf16(float* c,
    unsigned a0, unsigned a1, unsigned a2, unsigned a3,
    unsigned b0, unsigned b1)
{
    asm volatile(
        "mma.sync.aligned.m16n8k16.row.col.f32.bf16.bf16.f32 "
        "{%0,%1,%2,%3}, {%4,%5,%6,%7}, {%8,%9}, {%0,%1,%2,%3};\n"
        : "+f"(c[0]), "+f"(c[1]), "+f"(c[2]), "+f"(c[3])
        : "r"(a0), "r"(a1), "r"(a2), "r"(a3), "r"(b0), "r"(b1));
}

__device__ __forceinline__ unsigned f2tf(float x) {
    unsigned r;
    asm("cvt.rna.tf32.f32 %0, %1;" : "=r"(r) : "f"(x));
    return r;
}
__device__ __forceinline__ float f2tff(float x) { return __uint_as_float(f2tf(x)); }

__device__ __forceinline__ void mma_tf32(float* c,
    unsigned a0, unsigned a1, unsigned a2, unsigned a3,
    unsigned b0, unsigned b1)
{
    asm volatile(
        "mma.sync.aligned.m16n8k8.row.col.f32.tf32.tf32.f32 "
        "{%0,%1,%2,%3}, {%4,%5,%6,%7}, {%8,%9}, {%0,%1,%2,%3};\n"
        : "+f"(c[0]), "+f"(c[1]), "+f"(c[2]), "+f"(c[3])
        : "r"(a0), "r"(a1), "r"(a2), "r"(a3), "r"(b0), "r"(b1));
}

__device__ __forceinline__ void gemm_tc_body(
    const float* __restrict__ A, const float* __restrict__ W,
    const float* __restrict__ bias, const float* __restrict__ resp,
    float* __restrict__ Cout,
    int N, int K, int epi, unsigned* sm_u)
{
    unsigned* As = sm_u;
    unsigned* Bs = sm_u + 2*16*AS2_LD;

    const int tid = threadIdx.x;
    const int lane = tid & 31, wid = tid >> 5;
    const int wm = (wid >> 1) * 32;
    const int wn = (wid & 1) * 32;
    const int m0 = blockIdx.y * 128, n0 = blockIdx.x * 64;
    const int gr = lane >> 2, gc = lane & 3;

    const int arow = tid >> 3;
    const int aq   = (tid & 7) * 4;
    const int ap   = (tid & 7) * 2;
    const int wkp  = tid >> 4;
    const int wq   = (tid & 15) * 4;

    const float* Aptr = A + (long long)(m0 + arow)*K + aq;
    const float* Wp0  = W + (long long)(2*wkp  )*N + n0 + wq;
    const float* Wp1  = W + (long long)(2*wkp+1)*N + n0 + wq;
    const long long aRowStride32 = (long long)32*K;

    float4 ra[4], rw0, rw1;
    #pragma unroll
    for (int i = 0; i < 4; i++) ra[i] = *(const float4*)(Aptr + i*aRowStride32);
    rw0 = *(const float4*)(Wp0);
    rw1 = *(const float4*)(Wp1);

    #pragma unroll
    for (int i = 0; i < 4; i++) {
        int m = arow + i*32;
        As[(ap+0)*AS2_LD + m] = pkbf(ra[i].x, ra[i].y);
        As[(ap+1)*AS2_LD + m] = pkbf(ra[i].z, ra[i].w);
    }
    {
        uint4 bv;
        bv.x = pkbf(rw0.x, rw1.x); bv.y = pkbf(rw0.y, rw1.y);
        bv.z = pkbf(rw0.z, rw1.z); bv.w = pkbf(rw0.w, rw1.w);
        *(uint4*)&Bs[wkp*BS2_LD + wq] = bv;
    }
    __syncthreads();

    float acc[2][4][4];
    #pragma unroll
    for (int mt = 0; mt < 2; mt++)
        #pragma unroll
        for (int nt = 0; nt < 4; nt++)
            #pragma unroll
            for (int j = 0; j < 4; j++) acc[mt][nt][j] = 0.f;

    int buf = 0;
    for (int k0 = 0; k0 < K; k0 += TCK) {
        const bool has_next = (k0 + TCK) < K;
        if (has_next) {
            #pragma unroll
            for (int i = 0; i < 4; i++) ra[i] = *(const float4*)(Aptr + i*aRowStride32 + k0 + TCK);
            rw0 = *(const float4*)(Wp0 + (long long)(k0 + TCK)*N);
            rw1 = *(const float4*)(Wp1 + (long long)(k0 + TCK)*N);
        }

        const unsigned* Ab = As + buf*16*AS2_LD;
        const unsigned* Bb2 = Bs + buf*16*BS2_LD;
        #pragma unroll
        for (int kk2 = 0; kk2 < 16; kk2 += 8) {
            unsigned af[2][4];
            #pragma unroll
            for (int mt = 0; mt < 2; mt++) {
                int rb = wm + mt*16 + gr;
                af[mt][0] = Ab[(kk2+gc  )*AS2_LD + rb    ];
                af[mt][1] = Ab[(kk2+gc  )*AS2_LD + rb + 8];
                af[mt][2] = Ab[(kk2+gc+4)*AS2_LD + rb    ];
                af[mt][3] = Ab[(kk2+gc+4)*AS2_LD + rb + 8];
            }
            #pragma unroll
            for (int nt = 0; nt < 4; nt++) {
                int cb = wn + nt*8 + gr;
                unsigned b0 = Bb2[(kk2+gc  )*BS2_LD + cb];
                unsigned b1 = Bb2[(kk2+gc+4)*BS2_LD + cb];
                mma_bf16(acc[0][nt], af[0][0], af[0][1], af[0][2], af[0][3], b0, b1);
                mma_bf16(acc[1][nt], af[1][0], af[1][1], af[1][2], af[1][3], b0, b1);
            }
        }

        if (has_next) {
            int nb = buf ^ 1;
            unsigned* An = As + nb*16*AS2_LD;
            unsigned* Bn = Bs + nb*16*BS2_LD;
            #pragma unroll
            for (int i = 0; i < 4; i++) {
                int m = arow + i*32;
                An[(ap+0)*AS2_LD + m] = pkbf(ra[i].x, ra[i].y);
                An[(ap+1)*AS2_LD + m] = pkbf(ra[i].z, ra[i].w);
            }
            uint4 bv;
            bv.x = pkbf(rw0.x, rw1.x); bv.y = pkbf(rw0.y, rw1.y);
            bv.z = pkbf(rw0.z, rw1.z); bv.w = pkbf(rw0.w, rw1.w);
            *(uint4*)&Bn[wkp*BS2_LD + wq] = bv;
        }
        __syncthreads();
        buf ^= 1;
    }

    #pragma unroll
    for (int mt = 0; mt < 2; mt++) {
        #pragma unroll
        for (int nt = 0; nt < 4; nt++) {
            int col = n0 + wn + nt*8 + gc*2;
            float b0 = 0.f, b1 = 0.f;
            if (bias) { b0 = bias[col]; b1 = bias[col+1]; }
            #pragma unroll
            for (int half = 0; half < 2; half++) {
                int m = m0 + wm + mt*16 + gr + half*8;
                long long off = (long long)m*N + col;
                float c0 = acc[mt][nt][half*2+0] + b0;
                float c1 = acc[mt][nt][half*2+1] + b1;
                if (epi == 1) {
                    c0 = 0.5f*c0*(1.0f + erff(c0*0.70710678118654752f));
                    c1 = 0.5f*c1*(1.0f + erff(c1*0.70710678118654752f));
                } else if (epi == 2) {
                    float2 rr = *(const float2*)(resp + off);
                    c0 += rr.x; c1 += rr.y;
                }
                float2 o; o.x = c0; o.y = c1;
                *(float2*)(Cout + off) = o;
            }
        }
    }
}

__global__ void __launch_bounds__(256) gemm_tc_kernel(
    const float* __restrict__ A, const float* __restrict__ W,
    const float* __restrict__ bias, const float* __restrict__ res,
    float* __restrict__ Cout,
    int M, int N, int K, int epi)
{
    extern __shared__ unsigned sm_u[];
    gemm_tc_body(A, W, bias, res, Cout, N, K, epi, sm_u);
}

// QKV batched: blockIdx.z selects projection -> 3x the grid, one launch
__global__ void __launch_bounds__(256) qkv_tc_kernel(
    const float* __restrict__ A,
    const float* __restrict__ Wq, const float* __restrict__ bq, float* __restrict__ qO,
    const float* __restrict__ Wk, const float* __restrict__ bk, float* __restrict__ kO,
    const float* __restrict__ Wv, const float* __restrict__ bv, float* __restrict__ vO)
{
    extern __shared__ unsigned sm_u[];
    const float* W; const float* b; float* C;
    if (blockIdx.z == 0)      { W = Wq; b = bq; C = qO; }
    else if (blockIdx.z == 1) { W = Wk; b = bk; C = kO; }
    else                      { W = Wv; b = bv; C = vO; }
    gemm_tc_body(A, W, b, nullptr, C, Ss, Ss, 0, sm_u);
}

// ---------------- fused vattn: (0.25*sum_h linv*probs) @ vmix, bf16 MMA ------
// 32-row M tile -> grid 256 CTAs (was 128; 20 SMs sat idle).
#define VAT_AS2_LD 36       // [16 pairs][32 m + pad] uints
#define VAT_BS2_LD 196      // [16 pairs][192 n + pad] uints
#define VATTN_SMEM ((2*16*VAT_AS2_LD + 2*16*VAT_BS2_LD + 128)*4)

__global__ void __launch_bounds__(256) vattn_tc_kernel(
    const __nv_bfloat16* __restrict__ pg, const float* __restrict__ linvG,
    const float* __restrict__ vmix, float* __restrict__ va)
{
    extern __shared__ unsigned sv_u[];
    unsigned* As = sv_u;                          // [2][16][36]
    unsigned* Bs = sv_u + 2*16*VAT_AS2_LD;        // [2][16][196]
    float* linv_s = (float*)(sv_u + 2*16*VAT_AS2_LD + 2*16*VAT_BS2_LD);  // [4][32]

    const int b  = blockIdx.y;
    const int i0 = blockIdx.x * 32;
    const int tid = threadIdx.x;
    const int lane = tid & 31, wid = tid >> 5;
    const int wm = (wid >> 2) * 16;               // 0 / 16
    const int wn = (wid & 3) * 48;                // 0 / 48 / 96 / 144
    const int gr = lane >> 2, gc = lane & 3;

    const size_t pstride = (size_t)Nn * Nn;
    const __nv_bfloat16* pb = pg + (size_t)b*4*pstride + (size_t)i0*Nn;
    const float* vb = vmix + (size_t)b*Nn*192;

    if (tid < 128) {
        int hh = tid >> 5, ii = tid & 31;
        linv_s[hh*32 + ii] = 0.25f * linvG[(size_t)(b*4 + hh)*Nn + i0 + ii];
    }
    __syncthreads();

    // A loader: row = tid>>3 (0..31), 4 k-floats = 2 pairs per thread
    const int arow = tid >> 3;
    const int akq  = (tid & 7) * 4;
    const int app  = (tid & 7) * 2;
    float lr[4];
    #pragma unroll
    for (int h = 0; h < 4; h++) lr[h] = linv_s[h*32 + arow];
    const __nv_bfloat16* arp = pb + (size_t)arow*Nn + akq;

    // B loader: 3 groups; each = one k-pair x 4 cols
    int bk[3], bc[3];
    #pragma unroll
    for (int t = 0; t < 3; t++) {
        int idx = tid + t*256;
        bk[t] = idx / 48;
        bc[t] = (idx - bk[t]*48) * 4;
    }

    uint2 pa[4];
    float4 rb0[3], rb1[3];
    #pragma unroll
    for (int h = 0; h < 4; h++) pa[h] = *(const uint2*)(arp + h*pstride);
    #pragma unroll
    for (int t = 0; t < 3; t++) {
        rb0[t] = *(const float4*)(vb + (size_t)(2*bk[t]  )*192 + bc[t]);
        rb1[t] = *(const float4*)(vb + (size_t)(2*bk[t]+1)*192 + bc[t]);
    }

    {
        float f[4] = {0,0,0,0};
        #pragma unroll
        for (int h = 0; h < 4; h++) {
            const __nv_bfloat162* pp2 = (const __nv_bfloat162*)&pa[h];
            float lh = lr[h];
            #pragma unroll
            for (int t = 0; t < 2; t++) {
                float2 xy = __bfloat1622float2(pp2[t]);
                f[t*2+0] += lh*xy.x; f[t*2+1] += lh*xy.y;
            }
        }
        As[(app+0)*VAT_AS2_LD + arow] = pkbf(f[0], f[1]);
        As[(app+1)*VAT_AS2_LD + arow] = pkbf(f[2], f[3]);
        #pragma unroll
        for (int t = 0; t < 3; t++) {
            uint4 bv;
            bv.x = pkbf(rb0[t].x, rb1[t].x); bv.y = pkbf(rb0[t].y, rb1[t].y);
            bv.z = pkbf(rb0[t].z, rb1[t].z); bv.w = pkbf(rb0[t].w, rb1[t].w);
            *(uint4*)&Bs[bk[t]*VAT_BS2_LD + bc[t]] = bv;
        }
    }
    __syncthreads();

    float acc[6][4];
    #pragma unroll
    for (int nt = 0; nt < 6; nt++)
        #pragma unroll
        for (int j = 0; j < 4; j++) acc[nt][j] = 0.f;

    int buf = 0;
    for (int k0 = 0; k0 < Nn; k0 += TCK) {
        const bool has_next = (k0 + TCK) < Nn;
        if (has_next) {
            #pragma unroll
            for (int h = 0; h < 4; h++) pa[h] = *(const uint2*)(arp + h*pstride + k0 + TCK);
            #pragma unroll
            for (int t = 0; t < 3; t++) {
                rb0[t] = *(const float4*)(vb + (size_t)(k0 + TCK + 2*bk[t]  )*192 + bc[t]);
                rb1[t] = *(const float4*)(vb + (size_t)(k0 + TCK + 2*bk[t]+1)*192 + bc[t]);
            }
        }

        const unsigned* Ab  = As + buf*16*VAT_AS2_LD;
        const unsigned* Bb2 = Bs + buf*16*VAT_BS2_LD;
        #pragma unroll
        for (int kk2 = 0; kk2 < 16; kk2 += 8) {
            unsigned af[4];
            {
                int rb = wm + gr;
                af[0] = Ab[(kk2+gc  )*VAT_AS2_LD + rb    ];
                af[1] = Ab[(kk2+gc  )*VAT_AS2_LD + rb + 8];
                af[2] = Ab[(kk2+gc+4)*VAT_AS2_LD + rb    ];
                af[3] = Ab[(kk2+gc+4)*VAT_AS2_LD + rb + 8];
            }
            #pragma unroll
            for (int nt = 0; nt < 6; nt++) {
                int cb = wn + nt*8 + gr;
                unsigned b0 = Bb2[(kk2+gc  )*VAT_BS2_LD + cb];
                unsigned b1 = Bb2[(kk2+gc+4)*VAT_BS2_LD + cb];
                mma_bf16(acc[nt], af[0], af[1], af[2], af[3], b0, b1);
            }
        }

        if (has_next) {
            int nb = buf ^ 1;
            unsigned* An = As + nb*16*VAT_AS2_LD;
            unsigned* Bn = Bs + nb*16*VAT_BS2_LD;
            float f[4] = {0,0,0,0};
            #pragma unroll
            for (int h = 0; h < 4; h++) {
                const __nv_bfloat162* pp2 = (const __nv_bfloat162*)&pa[h];
                float lh = lr[h];
                #pragma unroll
                for (int t = 0; t < 2; t++) {
                    float2 xy = __bfloat1622float2(pp2[t]);
                    f[t*2+0] += lh*xy.x; f[t*2+1] += lh*xy.y;
                }
            }
            An[(app+0)*VAT_AS2_LD + arow] = pkbf(f[0], f[1]);
            An[(app+1)*VAT_AS2_LD + arow] = pkbf(f[2], f[3]);
            #pragma unroll
            for (int t = 0; t < 3; t++) {
                uint4 bv;
                bv.x = pkbf(rb0[t].x, rb1[t].x); bv.y = pkbf(rb0[t].y, rb1[t].y);
                bv.z = pkbf(rb0[t].z, rb1[t].z); bv.w = pkbf(rb0[t].w, rb1[t].w);
                *(uint4*)&Bn[bk[t]*VAT_BS2_LD + bc[t]] = bv;
            }
        }
        __syncthreads();
        buf ^= 1;
    }

    #pragma unroll
    for (int nt = 0; nt < 6; nt++) {
        int col = wn + nt*8 + gc*2;
        #pragma unroll
        for (int half = 0; half < 2; half++) {
            int m = wm + gr + half*8;
            float2 o;
            o.x = acc[nt][half*2+0];
            o.y = acc[nt][half*2+1];
            *(float2*)(va + ((size_t)b*Nn + i0 + m)*192 + col) = o;
        }
    }
}

// ---------------- small per-row channel mixes -------------------------------
__global__ void __launch_bounds__(192) vout_kernel(
    const float* __restrict__ vattn, const float* __restrict__ Wvo,
    const float* __restrict__ vin, float* __restrict__ outv)
{
    long long row = blockIdx.x;
    int tid = threadIdx.x;
    __shared__ float vrow[192];
    vrow[tid] = vattn[row*192 + tid];
    __syncthreads();
    int x = tid >> 6, e = tid & 63;
    float acc = 0.f;
    #pragma unroll 8
    for (int c = 0; c < 64; c++) acc += vrow[c*3 + x] * Wvo[c*64 + e];
    outv[row*192 + e*3 + x] = vin[row*192 + e*3 + x] + acc;
}

// 4 rows per CTA, register-blocked weight reuse
__global__ void __launch_bounds__(256) vffn_kernel(
    const float* __restrict__ vn, const float* __restrict__ Wfv1,
    const float* __restrict__ Wfv2, float* __restrict__ outv)
{
    long long row0 = (long long)blockIdx.x * 4;
    int tid = threadIdx.x;
    __shared__ float vrow[4][192];
    __shared__ float t[12][260];

    for (int idx = tid; idx < 768; idx += 256) {
        int r = idx / 192, j = idx - r*192;
        vrow[r][j] = vn[(row0 + r)*192 + j];
    }
    __syncthreads();

    {
        float acc[12];
        #pragma unroll
        for (int j = 0; j < 12; j++) acc[j] = 0.f;
        #pragma unroll 4
        for (int c = 0; c < 64; c++) {
            float w = Wfv1[c*256 + tid];
            #pragma unroll
            for (int r = 0; r < 4; r++)
                #pragma unroll
                for (int x = 0; x < 3; x++)
                    acc[r*3+x] += vrow[r][c*3+x] * w;
        }
        #pragma unroll
        for (int j = 0; j < 12; j++) t[j][tid] = acc[j];
    }
    __syncthreads();

    {
        int c = tid & 63, r = tid >> 6;
        float acc[3] = {0.f, 0.f, 0.f};
        #pragma unroll 4
        for (int h = 0; h < 256; h++) {
            float w2 = Wfv2[h*64 + c];
            #pragma unroll
            for (int x = 0; x < 3; x++)
                acc[x] += t[r*3+x][h] * w2;
        }
        #pragma unroll
        for (int x = 0; x < 3; x++)
            outv[(row0 + r)*192 + c*3 + x] += acc[x];
    }
}

// ---------------- fused attention: tf32 MMA flash, cp.async pipeline ---------
#define ATK 32
#define Q_LD 260
#define K_LD 260
#define V_LD 264
#define PS2_LD 36
#define ATTN_SMEM_FLOATS (64*Q_LD + 2*32*K_LD + 32*V_LD + 4*64*PS2_LD + 256 + 256)

__global__ void __launch_bounds__(256) attn_kernel(
    const float* __restrict__ qg, const float* __restrict__ kg,
    const float* __restrict__ vg, const float* __restrict__ pos,
    const float* __restrict__ wdist, const float* __restrict__ bdist,
    __nv_bfloat16* __restrict__ probsG, float* __restrict__ linvG,
    float* __restrict__ sattn)
{
    extern __shared__ float sm[];
    float* q_s  = sm;                        // [64][260] tf32 (RN cvt)
    float* k_s  = q_s + 64*Q_LD;             // [2][32][260] raw fp32
    float* v_s  = k_s + 2*32*K_LD;           // [32][264] raw fp32
    float* ps   = v_s + 32*V_LD;             // [4][64][36]
    float* posi = ps + 4*64*PS2_LD;          // [64][4]
    float* posm = posi + 256;                // [2][32][4]

    const int b  = blockIdx.y;
    const int n0 = blockIdx.x * 64;
    const int tid = threadIdx.x;
    const int lane = tid & 31, wid = tid >> 5;
    const int h  = wid >> 1;
    const int wm = (wid & 1) * 32;
    const int gr = lane >> 2, gc = lane & 3;
    const long long bofs = (long long)b * Nn;

    for (int idx = tid; idx < 4096; idx += 256) {
        int i = idx >> 6, d4 = (idx & 63) << 2;
        float4 qv = *(const float4*)(qg + (bofs + n0 + i)*Ss + d4);
        float* dst = q_s + i*Q_LD + d4;
        dst[0] = f2tff(qv.x); dst[1] = f2tff(qv.y);
        dst[2] = f2tff(qv.z); dst[3] = f2tff(qv.w);
    }
    if (tid < 64) {
        const float* pp = pos + (bofs + n0 + tid)*3;
        float a = pp[0], b2 = pp[1], c = pp[2];
        posi[tid*4+0]=a; posi[tid*4+1]=b2; posi[tid*4+2]=c; posi[tid*4+3]=a*a+b2*b2+c*c;
    }
    const float wh = wdist[h], bh = bdist[h];

    float accO[2][8][4];
    #pragma unroll
    for (int mt = 0; mt < 2; mt++)
        #pragma unroll
        for (int nt = 0; nt < 8; nt++)
            #pragma unroll
            for (int j = 0; j < 4; j++) accO[mt][nt][j] = 0.f;
    float rs[2][2] = {{0.f,0.f},{0.f,0.f}};

    __nv_bfloat16* pgbase = probsG + ((size_t)(b*4 + h)*Nn + n0)*Nn;
    float* psh = ps + h*64*PS2_LD;

    {
        const float* kgp = kg + bofs*Ss;
        for (int idx = tid; idx < 2048; idx += 256) {
            int m = idx >> 6, d4 = (idx & 63) << 2;
            cp16(k_s + m*K_LD + d4, kgp + (long long)m*Ss + d4);
        }
        CP_COMMIT();
        if (tid < 32) {
            const float* pp = pos + (bofs + tid)*3;
            float a = pp[0], b2 = pp[1], c = pp[2];
            posm[tid*4+0]=a; posm[tid*4+1]=b2; posm[tid*4+2]=c; posm[tid*4+3]=a*a+b2*b2+c*c;
        }
    }

    for (int t64 = 0; t64 < 64; t64++) {
        const int m0g = t64 * ATK;
        const int kb = t64 & 1;
        const bool more = (t64 + 1) < 64;

        CP_WAIT0();
        __syncthreads();

        {
            const float* vgp = vg + (bofs + m0g)*(long long)Ss;
            for (int idx = tid; idx < 2048; idx += 256) {
                int m = idx >> 6, d4 = (idx & 63) << 2;
                cp16(v_s + m*V_LD + d4, vgp + (long long)m*Ss + d4);
            }
            CP_COMMIT();
        }
        if (more) {
            const float* kgp = kg + (bofs + m0g + ATK)*(long long)Ss;
            float* kd = k_s + (kb^1)*32*K_LD;
            for (int idx = tid; idx < 2048; idx += 256) {
                int m = idx >> 6, d4 = (idx & 63) << 2;
                cp16(kd + m*K_LD + d4, kgp + (long long)m*Ss + d4);
            }
            CP_COMMIT();
            if (tid < 32) {
                const float* pp = pos + (bofs + m0g + ATK + tid)*3;
                float a = pp[0], b2 = pp[1], c = pp[2];
                float* pm = posm + (kb^1)*128;
                pm[tid*4+0]=a; pm[tid*4+1]=b2; pm[tid*4+2]=c; pm[tid*4+3]=a*a+b2*b2+c*c;
            }
        }

        const float* kbuf = k_s + kb*32*K_LD;
        const float* pmv_buf = posm + kb*128;

        float acc[2][4][4];
        #pragma unroll
        for (int mt = 0; mt < 2; mt++)
            #pragma unroll
            for (int nt = 0; nt < 4; nt++)
                #pragma unroll
                for (int j = 0; j < 4; j++) acc[mt][nt][j] = 0.f;

        #pragma unroll
        for (int kk = 0; kk < 64; kk += 8) {
            unsigned af[2][4];
            #pragma unroll
            for (int mt = 0; mt < 2; mt++) {
                const float* qp = q_s + (wm + mt*16 + gr)*Q_LD + h*64 + kk + gc;
                af[mt][0] = __float_as_uint(qp[0]);
                af[mt][1] = __float_as_uint(qp[8*Q_LD]);
                af[mt][2] = __float_as_uint(qp[4]);
                af[mt][3] = __float_as_uint(qp[8*Q_LD+4]);
            }
            #pragma unroll
            for (int nt = 0; nt < 4; nt++) {
                const float* kp = kbuf + (nt*8 + gr)*K_LD + h*64 + kk + gc;
                unsigned b0 = __float_as_uint(kp[0]);
                unsigned b1 = __float_as_uint(kp[4]);
                mma_tf32(acc[0][nt], af[0][0], af[0][1], af[0][2], af[0][3], b0, b1);
                mma_tf32(acc[1][nt], af[1][0], af[1][1], af[1][2], af[1][3], b0, b1);
            }
        }

        #pragma unroll
        for (int mt = 0; mt < 2; mt++) {
            int r0 = wm + mt*16 + gr;
            float4 pi0 = ((const float4*)posi)[r0];
            float4 pi1 = ((const float4*)posi)[r0+8];
            #pragma unroll
            for (int nt = 0; nt < 4; nt++) {
                int mloc = nt*8 + gc*2;
                float4 pm0 = ((const float4*)pmv_buf)[mloc];
                float4 pm1 = ((const float4*)pmv_buf)[mloc+1];
                float p4[4];
                #pragma unroll
                for (int e = 0; e < 4; e++) {
                    float4 pi = (e < 2) ? pi0 : pi1;
                    float4 pm = (e & 1) ? pm1 : pm0;
                    float d2 = pi.w + pm.w - 2.f*(pi.x*pm.x + pi.y*pm.y + pi.z*pm.z);
                    d2 = fmaxf(d2, 1e-12f);
                    float dist = d2 * rsqrtf(d2);
                    float sx = dist*wh + bh;
                    float sg = __fdividef(1.f, 1.f + __expf(sx));
                    p4[e] = __expf(acc[mt][nt][e]*0.125f) * sg;
                }
                rs[mt][0] += p4[0] + p4[1];
                rs[mt][1] += p4[2] + p4[3];
                *(float2*)(psh + r0*PS2_LD + mloc) = make_float2(f2tff(p4[0]), f2tff(p4[1]));
                *(float2*)(psh + (r0+8)*PS2_LD + mloc) = make_float2(f2tff(p4[2]), f2tff(p4[3]));
                __nv_bfloat162 q01 = __floats2bfloat162_rn(p4[0], p4[1]);
                __nv_bfloat162 q23 = __floats2bfloat162_rn(p4[2], p4[3]);
                __stcs((unsigned int*)(pgbase + (size_t)r0*Nn + m0g + mloc),
                       *(unsigned int*)&q01);
                __stcs((unsigned int*)(pgbase + (size_t)(r0+8)*Nn + m0g + mloc),
                       *(unsigned int*)&q23);
            }
        }

        if (more) { CP_WAIT1(); } else { CP_WAIT0(); }
        __syncthreads();

        #pragma unroll
        for (int kk = 0; kk < 32; kk += 8) {
            unsigned af[2][4];
            #pragma unroll
            for (int mt = 0; mt < 2; mt++) {
                const float* pp = psh + (wm + mt*16 + gr)*PS2_LD + kk + gc;
                af[mt][0] = __float_as_uint(pp[0]);
                af[mt][1] = __float_as_uint(pp[8*PS2_LD]);
                af[mt][2] = __float_as_uint(pp[4]);
                af[mt][3] = __float_as_uint(pp[8*PS2_LD+4]);
            }
            #pragma unroll
            for (int nt = 0; nt < 8; nt++) {
                const float* vp2 = v_s + (kk+gc)*V_LD + h*64 + nt*8 + gr;
                unsigned b0 = __float_as_uint(vp2[0]);
                unsigned b1 = __float_as_uint(vp2[4*V_LD]);
                mma_tf32(accO[0][nt], af[0][0], af[0][1], af[0][2], af[0][3], b0, b1);
                mma_tf32(accO[1][nt], af[1][0], af[1][1], af[1][2], af[1][3], b0, b1);
            }
        }
    }

    float linv[2][2];
    #pragma unroll
    for (int mt = 0; mt < 2; mt++)
        #pragma unroll
        for (int hh = 0; hh < 2; hh++) {
            float v = rs[mt][hh];
            v += __shfl_xor_sync(0xffffffffu, v, 1);
            v += __shfl_xor_sync(0xffffffffu, v, 2);
            linv[mt][hh] = __fdividef(1.f, v);
        }
    if (gc == 0) {
        #pragma unroll
        for (int mt = 0; mt < 2; mt++) {
            int r0 = wm + mt*16 + gr;
            linvG[(size_t)(b*4 + h)*Nn + n0 + r0]     = linv[mt][0];
            linvG[(size_t)(b*4 + h)*Nn + n0 + r0 + 8] = linv[mt][1];
        }
    }
    #pragma unroll
    for (int mt = 0; mt < 2; mt++) {
        #pragma unroll
        for (int nt = 0; nt < 8; nt++) {
            int col = h*64 + nt*8 + gc*2;
            int r0 = wm + mt*16 + gr;
            float2 o0, o1;
            o0.x = accO[mt][nt][0]*linv[mt][0];
            o0.y = accO[mt][nt][1]*linv[mt][0];
            o1.x = accO[mt][nt][2]*linv[mt][1];
            o1.y = accO[mt][nt][3]*linv[mt][1];
            *(float2*)(sattn + (bofs + n0 + r0)*Ss + col) = o0;
            *(float2*)(sattn + (bofs + n0 + r0 + 8)*Ss + col) = o1;
        }
    }
}

// ---------------- launch ------------------------------------------------------
extern "C" void kernel_launch(void* const* d_in, const int* in_sizes, int n_in,
                              void* d_out, int out_size)
{
    const float* s_in  = (const float*)d_in[0];
    const float* v_in  = (const float*)d_in[1];
    const float* pos   = (const float*)d_in[2];
    const float* Wq    = (const float*)d_in[3];
    const float* bq    = (const float*)d_in[4];
    const float* Wk    = (const float*)d_in[5];
    const float* bk    = (const float*)d_in[6];
    const float* Wv    = (const float*)d_in[7];
    const float* bv    = (const float*)d_in[8];
    const float* Wo    = (const float*)d_in[9];
    const float* bo    = (const float*)d_in[10];
    const float* wdist = (const float*)d_in[11];
    const float* bdist = (const float*)d_in[12];
    const float* Wvv   = (const float*)d_in[13];
    const float* Wvo   = (const float*)d_in[14];
    const float* g1    = (const float*)d_in[15];
    const float* be1   = (const float*)d_in[16];
    const float* vs1   = (const float*)d_in[17];
    const float* g2    = (const float*)d_in[18];
    const float* be2   = (const float*)d_in[19];
    const float* vs2   = (const float*)d_in[20];
    const float* Wf1   = (const float*)d_in[21];
    const float* bf1   = (const float*)d_in[22];
    const float* Wf2   = (const float*)d_in[23];
    const float* bf2   = (const float*)d_in[24];
    const float* Wfv1  = (const float*)d_in[25];
    const float* Wfv2  = (const float*)d_in[26];

    float* out_s = (float*)d_out;
    float* out_v = out_s + (size_t)ROWS*Ss;

    void *p_sn, *p_vn, *p_q, *p_k, *p_vp, *p_vmix, *p_pb, *p_li, *p_sa, *p_va, *p_ffn;
    cudaGetSymbolAddress(&p_sn, g_sn);
    cudaGetSymbolAddress(&p_vn, g_vn);
    cudaGetSymbolAddress(&p_q,  g_q);
    cudaGetSymbolAddress(&p_k,  g_k);
    cudaGetSymbolAddress(&p_vp, g_vp);
    cudaGetSymbolAddress(&p_vmix, g_vmix);
    cudaGetSymbolAddress(&p_pb, g_probs);
    cudaGetSymbolAddress(&p_li, g_linv);
    cudaGetSymbolAddress(&p_sa, g_sattn);
    cudaGetSymbolAddress(&p_va, g_vattn);
    cudaGetSymbolAddress(&p_ffn, g_ffn);
    float* sn   = (float*)p_sn;   float* vn   = (float*)p_vn;
    float* q    = (float*)p_q;    float* k    = (float*)p_k;
    float* vp   = (float*)p_vp;   float* vmix = (float*)p_vmix;
    __nv_bfloat16* pb = (__nv_bfloat16*)p_pb;
    float* li   = (float*)p_li;
    float* sa   = (float*)p_sa;   float* va   = (float*)p_va;
    float* ffn  = (float*)p_ffn;

    const int attn_smem = ATTN_SMEM_FLOATS * 4;
    cudaFuncSetAttribute(attn_kernel, cudaFuncAttributeMaxDynamicSharedMemorySize, attn_smem);
    cudaFuncSetAttribute(gemm_tc_kernel, cudaFuncAttributeMaxDynamicSharedMemorySize, GEMM_TC_SMEM);
    cudaFuncSetAttribute(qkv_tc_kernel, cudaFuncAttributeMaxDynamicSharedMemorySize, GEMM_TC_SMEM);
    cudaFuncSetAttribute(vattn_tc_kernel, cudaFuncAttributeMaxDynamicSharedMemorySize, VATTN_SMEM);

    // 1) eq-LN #1 (+ fused vmix = vn @ Wvv)
    eqln_kernel<<<ROWS, 256>>>(s_in, v_in, g1, be1, vs1, sn, vn, Wvv, vmix);

    // 2) QKV projections, single batched launch (bf16 tensor cores)
    qkv_tc_kernel<<<dim3(Ss/64, ROWS/128, 3), 256, GEMM_TC_SMEM>>>(
        sn, Wq, bq, q, Wk, bk, k, Wv, bv, vp);

    // 3) fused single-pass tf32-MMA attention (cp.async pipelined)
    attn_kernel<<<dim3(Nn/64, Bb), 256, attn_smem>>>(q, k, vp, pos, wdist, bdist, pb, li, sa);

    // 4) fused v_attn = (0.25*sum_h linv*probs) @ vmix  (bf16 MMA, 32-row tiles)
    vattn_tc_kernel<<<dim3(Nn/32, Bb), 256, VATTN_SMEM>>>(pb, li, vmix, va);

    // 5) out_s = s_in + sattn @ Wo + bo
    gemm_tc_kernel<<<dim3(Ss/64, ROWS/128, 1), 256, GEMM_TC_SMEM>>>(sa, Wo, bo, s_in, out_s, ROWS, Ss, Ss, 2);

    // 6) out_v = v_in + v_attn @ Wvo
    vout_kernel<<<ROWS, 192>>>(va, Wvo, v_in, out_v);

    // 7) eq-LN #2 (no vmix)
    eqln_kernel<<<ROWS, 256>>>(out_s, out_v, g2, be2, vs2, sn, vn, nullptr, nullptr);

    // 8) FFN (bf16 tensor cores, GELU + residual epilogues)
    gemm_tc_kernel<<<dim3(Ff/64, ROWS/128, 1), 256, GEMM_TC_SMEM>>>(sn, Wf1, bf1, nullptr, ffn, ROWS, Ff, Ss, 1);
    gemm_tc_kernel<<<dim3(Ss/64, ROWS/128, 1), 256, GEMM_TC_SMEM>>>(ffn, Wf2, bf2, out_s, out_s, ROWS, Ss, Ff, 2);

    // 9) vector FFN (4 rows per CTA)
    vffn_kernel<<<ROWS/4, 256>>>(vn, Wfv1, Wfv2, out_v);
}

// round 17
// speedup vs baseline: 1.0323x; 1.0323x over previous
#include <cuda_runtime.h>
#include <cuda_bf16.h>
#include <math.h>

#define Bb   4
#define Nn   2048
#define Ss   256
#define Cc   64
#define Hh   4
#define Dd   64
#define Ff   1024
#define ROWS (Bb*Nn)          // 8192
#define KSPLIT 4

// ---------------- scratch (static device memory; no allocations) -------------
__device__ float g_sn[ROWS*Ss];
__device__ float g_vn[ROWS*Cc*3];
__device__ float g_q[ROWS*Ss];
__device__ float g_k[ROWS*Ss];
__device__ float g_vp[ROWS*Ss];
__device__ float g_vmix[ROWS*Cc*3];
__device__ __nv_bfloat16 g_probs[(size_t)Bb*Hh*Nn*Nn];   // 134 MB unnormalized probs
__device__ float g_linv[(size_t)Bb*Hh*Nn];
__device__ float g_sattn[ROWS*Ss];
__device__ float g_vattn[(size_t)KSPLIT*ROWS*Cc*3];       // K-split partials
__device__ float g_ffn[ROWS*Ff];

// ---------------- cp.async helpers -------------------------------------------
__device__ __forceinline__ void cp16(void* s, const void* g) {
    unsigned sa = (unsigned)__cvta_generic_to_shared(s);
    asm volatile("cp.async.cg.shared.global [%0], [%1], 16;\n" :: "r"(sa), "l"(g) : "memory");
}
#define CP_COMMIT() asm volatile("cp.async.commit_group;\n" ::: "memory")
#define CP_WAIT0()  asm volatile("cp.async.wait_group 0;\n" ::: "memory")
#define CP_WAIT1()  asm volatile("cp.async.wait_group 1;\n" ::: "memory")

// ---------------- eq layernorm (+ optional fused vmix) -----------------------
__global__ void __launch_bounds__(256) eqln_kernel(
    const float* __restrict__ sin, const float* __restrict__ vin,
    const float* __restrict__ g, const float* __restrict__ be,
    const float* __restrict__ vsc,
    float* __restrict__ sn, float* __restrict__ vn,
    const float* __restrict__ Wvv, float* __restrict__ vmixO)
{
    long long row = blockIdx.x;
    int tid = threadIdx.x;
    __shared__ float redA[8], redB[8], norms[64], st[3], vsh[192];

    float x = sin[row*Ss + tid];
    float s1 = x, s2 = x*x;
    #pragma unroll
    for (int o = 16; o; o >>= 1) {
        s1 += __shfl_xor_sync(0xffffffffu, s1, o);
        s2 += __shfl_xor_sync(0xffffffffu, s2, o);
    }
    if ((tid & 31) == 0) { redA[tid>>5] = s1; redB[tid>>5] = s2; }

    if (tid < 64) {
        const float* vp = vin + row*192 + tid*3;
        float a = vp[0], b2 = vp[1], c = vp[2];
        norms[tid] = sqrtf(a*a + b2*b2 + c*c);
    }
    __syncthreads();
    if (tid == 0) {
        float A = 0.f, Bs2 = 0.f;
        #pragma unroll
        for (int w = 0; w < 8; w++) { A += redA[w]; Bs2 += redB[w]; }
        float mu  = A * (1.f/256.f);
        float var = Bs2 * (1.f/256.f) - mu*mu;
        st[0] = mu; st[1] = rsqrtf(var + 1e-5f);
        float t = 0.f;
        for (int c = 0; c < 64; c++) t += norms[c];
        st[2] = t * (1.f/64.f);
    }
    __syncthreads();
    sn[row*Ss + tid] = (x - st[0]) * st[1] * g[tid] + be[tid];
    if (tid < 192) {
        int c = tid / 3;
        float val = vin[row*192 + tid] / (norms[c] + 1e-5f) * st[2] * vsc[c];
        vn[row*192 + tid] = val;
        vsh[tid] = val;
    }
    if (vmixO) {
        __syncthreads();
        if (tid < 192) {
            int xx = tid >> 6, e = tid & 63;
            float acc = 0.f;
            #pragma unroll 8
            for (int c = 0; c < 64; c++) acc += vsh[c*3 + xx] * Wvv[c*64 + e];
            vmixO[row*192 + e*3 + xx] = acc;
        }
    }
}

// ---------------- bf16 tensor-core GEMM: 128x64 CTA, mma.m16n8k16 ------------
#define TCK 32
#define AS2_LD 132
#define BS2_LD 68
#define GEMM_TC_SMEM ((2*16*AS2_LD + 2*16*BS2_LD)*4)

__device__ __forceinline__ unsigned pkbf(float x, float y) {
    __nv_bfloat162 h = __floats2bfloat162_rn(x, y);
    return *(unsigned*)&h;
}

__device__ __forceinline__ void mma_bf16(float* c,
    unsigned a0, unsigned a1, unsigned a2, unsigned a3,
    unsigned b0, unsigned b1)
{
    asm volatile(
        "mma.sync.aligned.m16n8k16.row.col.f32.bf16.bf16.f32 "
        "{%0,%1,%2,%3}, {%4,%5,%6,%7}, {%8,%9}, {%0,%1,%2,%3};\n"
        : "+f"(c[0]), "+f"(c[1]), "+f"(c[2]), "+f"(c[3])
        : "r"(a0), "r"(a1), "r"(a2), "r"(a3), "r"(b0), "r"(b1));
}

__device__ __forceinline__ unsigned f2tf(float x) {
    unsigned r;
    asm("cvt.rna.tf32.f32 %0, %1;" : "=r"(r) : "f"(x));
    return r;
}
__device__ __forceinline__ float f2tff(float x) { return __uint_as_float(f2tf(x)); }

__device__ __forceinline__ void mma_tf32(float* c,
    unsigned a0, unsigned a1, unsigned a2, unsigned a3,
    unsigned b0, unsigned b1)
{
    asm volatile(
        "mma.sync.aligned.m16n8k8.row.col.f32.tf32.tf32.f32 "
        "{%0,%1,%2,%3}, {%4,%5,%6,%7}, {%8,%9}, {%0,%1,%2,%3};\n"
        : "+f"(c[0]), "+f"(c[1]), "+f"(c[2]), "+f"(c[3])
        : "r"(a0), "r"(a1), "r"(a2), "r"(a3), "r"(b0), "r"(b1));
}

__device__ __forceinline__ void gemm_tc_body(
    const float* __restrict__ A, const float* __restrict__ W,
    const float* __restrict__ bias, const float* __restrict__ resp,
    float* __restrict__ Cout,
    int N, int K, int epi, unsigned* sm_u)
{
    unsigned* As = sm_u;
    unsigned* Bs = sm_u + 2*16*AS2_LD;

    const int tid = threadIdx.x;
    const int lane = tid & 31, wid = tid >> 5;
    const int wm = (wid >> 1) * 32;
    const int wn = (wid & 1) * 32;
    const int m0 = blockIdx.y * 128, n0 = blockIdx.x * 64;
    const int gr = lane >> 2, gc = lane & 3;

    const int arow = tid >> 3;
    const int aq   = (tid & 7) * 4;
    const int ap   = (tid & 7) * 2;
    const int wkp  = tid >> 4;
    const int wq   = (tid & 15) * 4;

    const float* Aptr = A + (long long)(m0 + arow)*K + aq;
    const float* Wp0  = W + (long long)(2*wkp  )*N + n0 + wq;
    const float* Wp1  = W + (long long)(2*wkp+1)*N + n0 + wq;
    const long long aRowStride32 = (long long)32*K;

    float4 ra[4], rw0, rw1;
    #pragma unroll
    for (int i = 0; i < 4; i++) ra[i] = *(const float4*)(Aptr + i*aRowStride32);
    rw0 = *(const float4*)(Wp0);
    rw1 = *(const float4*)(Wp1);

    #pragma unroll
    for (int i = 0; i < 4; i++) {
        int m = arow + i*32;
        As[(ap+0)*AS2_LD + m] = pkbf(ra[i].x, ra[i].y);
        As[(ap+1)*AS2_LD + m] = pkbf(ra[i].z, ra[i].w);
    }
    {
        uint4 bv;
        bv.x = pkbf(rw0.x, rw1.x); bv.y = pkbf(rw0.y, rw1.y);
        bv.z = pkbf(rw0.z, rw1.z); bv.w = pkbf(rw0.w, rw1.w);
        *(uint4*)&Bs[wkp*BS2_LD + wq] = bv;
    }
    __syncthreads();

    float acc[2][4][4];
    #pragma unroll
    for (int mt = 0; mt < 2; mt++)
        #pragma unroll
        for (int nt = 0; nt < 4; nt++)
            #pragma unroll
            for (int j = 0; j < 4; j++) acc[mt][nt][j] = 0.f;

    int buf = 0;
    for (int k0 = 0; k0 < K; k0 += TCK) {
        const bool has_next = (k0 + TCK) < K;
        if (has_next) {
            #pragma unroll
            for (int i = 0; i < 4; i++) ra[i] = *(const float4*)(Aptr + i*aRowStride32 + k0 + TCK);
            rw0 = *(const float4*)(Wp0 + (long long)(k0 + TCK)*N);
            rw1 = *(const float4*)(Wp1 + (long long)(k0 + TCK)*N);
        }

        const unsigned* Ab = As + buf*16*AS2_LD;
        const unsigned* Bb2 = Bs + buf*16*BS2_LD;
        #pragma unroll
        for (int kk2 = 0; kk2 < 16; kk2 += 8) {
            unsigned af[2][4];
            #pragma unroll
            for (int mt = 0; mt < 2; mt++) {
                int rb = wm + mt*16 + gr;
                af[mt][0] = Ab[(kk2+gc  )*AS2_LD + rb    ];
                af[mt][1] = Ab[(kk2+gc  )*AS2_LD + rb + 8];
                af[mt][2] = Ab[(kk2+gc+4)*AS2_LD + rb    ];
                af[mt][3] = Ab[(kk2+gc+4)*AS2_LD + rb + 8];
            }
            #pragma unroll
            for (int nt = 0; nt < 4; nt++) {
                int cb = wn + nt*8 + gr;
                unsigned b0 = Bb2[(kk2+gc  )*BS2_LD + cb];
                unsigned b1 = Bb2[(kk2+gc+4)*BS2_LD + cb];
                mma_bf16(acc[0][nt], af[0][0], af[0][1], af[0][2], af[0][3], b0, b1);
                mma_bf16(acc[1][nt], af[1][0], af[1][1], af[1][2], af[1][3], b0, b1);
            }
        }

        if (has_next) {
            int nb = buf ^ 1;
            unsigned* An = As + nb*16*AS2_LD;
            unsigned* Bn = Bs + nb*16*BS2_LD;
            #pragma unroll
            for (int i = 0; i < 4; i++) {
                int m = arow + i*32;
                An[(ap+0)*AS2_LD + m] = pkbf(ra[i].x, ra[i].y);
                An[(ap+1)*AS2_LD + m] = pkbf(ra[i].z, ra[i].w);
            }
            uint4 bv;
            bv.x = pkbf(rw0.x, rw1.x); bv.y = pkbf(rw0.y, rw1.y);
            bv.z = pkbf(rw0.z, rw1.z); bv.w = pkbf(rw0.w, rw1.w);
            *(uint4*)&Bn[wkp*BS2_LD + wq] = bv;
        }
        __syncthreads();
        buf ^= 1;
    }

    #pragma unroll
    for (int mt = 0; mt < 2; mt++) {
        #pragma unroll
        for (int nt = 0; nt < 4; nt++) {
            int col = n0 + wn + nt*8 + gc*2;
            float b0 = 0.f, b1 = 0.f;
            if (bias) { b0 = bias[col]; b1 = bias[col+1]; }
            #pragma unroll
            for (int half = 0; half < 2; half++) {
                int m = m0 + wm + mt*16 + gr + half*8;
                long long off = (long long)m*N + col;
                float c0 = acc[mt][nt][half*2+0] + b0;
                float c1 = acc[mt][nt][half*2+1] + b1;
                if (epi == 1) {
                    c0 = 0.5f*c0*(1.0f + erff(c0*0.70710678118654752f));
                    c1 = 0.5f*c1*(1.0f + erff(c1*0.70710678118654752f));
                } else if (epi == 2) {
                    float2 rr = *(const float2*)(resp + off);
                    c0 += rr.x; c1 += rr.y;
                }
                float2 o; o.x = c0; o.y = c1;
                *(float2*)(Cout + off) = o;
            }
        }
    }
}

__global__ void __launch_bounds__(256) gemm_tc_kernel(
    const float* __restrict__ A, const float* __restrict__ W,
    const float* __restrict__ bias, const float* __restrict__ res,
    float* __restrict__ Cout,
    int M, int N, int K, int epi)
{
    extern __shared__ unsigned sm_u[];
    gemm_tc_body(A, W, bias, res, Cout, N, K, epi, sm_u);
}

// QKV batched: blockIdx.z selects projection
__global__ void __launch_bounds__(256) qkv_tc_kernel(
    const float* __restrict__ A,
    const float* __restrict__ Wq, const float* __restrict__ bq, float* __restrict__ qO,
    const float* __restrict__ Wk, const float* __restrict__ bk, float* __restrict__ kO,
    const float* __restrict__ Wv, const float* __restrict__ bv, float* __restrict__ vO)
{
    extern __shared__ unsigned sm_u[];
    const float* W; const float* b; float* C;
    if (blockIdx.z == 0)      { W = Wq; b = bq; C = qO; }
    else if (blockIdx.z == 1) { W = Wk; b = bk; C = kO; }
    else                      { W = Wv; b = bv; C = vO; }
    gemm_tc_body(A, W, b, nullptr, C, Ss, Ss, 0, sm_u);
}

// ---------------- fused vattn: (0.25*sum_h linv*probs) @ vmix, bf16 MMA ------
// 64-row M tile (R15 layout), 4-way K-split via blockIdx.z -> 512 CTAs.
// Partial z covers k in [z*512, (z+1)*512); vout sums the partials.
#define VAT_AS2_LD 68       // [16 pairs][64 m + pad] uints
#define VAT_BS2_LD 196      // [16 pairs][192 n + pad] uints
#define VATTN_SMEM ((2*16*VAT_AS2_LD + 2*16*VAT_BS2_LD + 256)*4)
#define KCHUNK (Nn/KSPLIT)   // 512

__global__ void __launch_bounds__(256, 2) vattn_tc_kernel(
    const __nv_bfloat16* __restrict__ pg, const float* __restrict__ linvG,
    const float* __restrict__ vmix, float* __restrict__ va)
{
    extern __shared__ unsigned sv_u[];
    unsigned* As = sv_u;                          // [2][16][68]
    unsigned* Bs = sv_u + 2*16*VAT_AS2_LD;        // [2][16][196]
    float* linv_s = (float*)(sv_u + 2*16*VAT_AS2_LD + 2*16*VAT_BS2_LD);

    const int b  = blockIdx.y;
    const int i0 = blockIdx.x * 64;
    const int kz = blockIdx.z;
    const int kbeg = kz * KCHUNK;
    const int tid = threadIdx.x;
    const int lane = tid & 31, wid = tid >> 5;
    const int wm = (wid >> 2) * 32;
    const int wn = (wid & 3) * 48;
    const int gr = lane >> 2, gc = lane & 3;

    const size_t pstride = (size_t)Nn * Nn;
    const __nv_bfloat16* pb = pg + (size_t)b*4*pstride + (size_t)i0*Nn;
    const float* vb = vmix + (size_t)b*Nn*192;

    {
        int hh = tid >> 6, ii = tid & 63;
        linv_s[hh*64 + ii] = 0.25f * linvG[(size_t)(b*4 + hh)*Nn + i0 + ii];
    }
    __syncthreads();

    const int arow = tid >> 2;
    const int akq  = (tid & 3) * 8;
    const int app  = (tid & 3) * 4;
    float lr[4];
    #pragma unroll
    for (int h = 0; h < 4; h++) lr[h] = linv_s[h*64 + arow];
    const __nv_bfloat16* arp = pb + (size_t)arow*Nn + akq + kbeg;

    int bk[3], bc[3];
    #pragma unroll
    for (int t = 0; t < 3; t++) {
        int idx = tid + t*256;
        bk[t] = idx / 48;
        bc[t] = (idx - bk[t]*48) * 4;
    }

    uint4 pa[4];
    float4 rb0[3], rb1[3];
    #pragma unroll
    for (int h = 0; h < 4; h++) pa[h] = *(const uint4*)(arp + h*pstride);
    #pragma unroll
    for (int t = 0; t < 3; t++) {
        rb0[t] = *(const float4*)(vb + (size_t)(kbeg + 2*bk[t]  )*192 + bc[t]);
        rb1[t] = *(const float4*)(vb + (size_t)(kbeg + 2*bk[t]+1)*192 + bc[t]);
    }

    {
        float f[8] = {0,0,0,0,0,0,0,0};
        #pragma unroll
        for (int h = 0; h < 4; h++) {
            const __nv_bfloat162* pp2 = (const __nv_bfloat162*)&pa[h];
            float lh = lr[h];
            #pragma unroll
            for (int t = 0; t < 4; t++) {
                float2 xy = __bfloat1622float2(pp2[t]);
                f[t*2+0] += lh*xy.x; f[t*2+1] += lh*xy.y;
            }
        }
        #pragma unroll
        for (int jj = 0; jj < 4; jj++)
            As[(app+jj)*VAT_AS2_LD + arow] = pkbf(f[2*jj], f[2*jj+1]);
        #pragma unroll
        for (int t = 0; t < 3; t++) {
            uint4 bv;
            bv.x = pkbf(rb0[t].x, rb1[t].x); bv.y = pkbf(rb0[t].y, rb1[t].y);
            bv.z = pkbf(rb0[t].z, rb1[t].z); bv.w = pkbf(rb0[t].w, rb1[t].w);
            *(uint4*)&Bs[bk[t]*VAT_BS2_LD + bc[t]] = bv;
        }
    }
    __syncthreads();

    float acc[2][6][4];
    #pragma unroll
    for (int mt = 0; mt < 2; mt++)
        #pragma unroll
        for (int nt = 0; nt < 6; nt++)
            #pragma unroll
            for (int j = 0; j < 4; j++) acc[mt][nt][j] = 0.f;

    int buf = 0;
    for (int k0r = 0; k0r < KCHUNK; k0r += TCK) {
        const bool has_next = (k0r + TCK) < KCHUNK;
        if (has_next) {
            #pragma unroll
            for (int h = 0; h < 4; h++) pa[h] = *(const uint4*)(arp + h*pstride + k0r + TCK);
            #pragma unroll
            for (int t = 0; t < 3; t++) {
                rb0[t] = *(const float4*)(vb + (size_t)(kbeg + k0r + TCK + 2*bk[t]  )*192 + bc[t]);
                rb1[t] = *(const float4*)(vb + (size_t)(kbeg + k0r + TCK + 2*bk[t]+1)*192 + bc[t]);
            }
        }

        const unsigned* Ab  = As + buf*16*VAT_AS2_LD;
        const unsigned* Bb2 = Bs + buf*16*VAT_BS2_LD;
        #pragma unroll
        for (int kk2 = 0; kk2 < 16; kk2 += 8) {
            unsigned af[2][4];
            #pragma unroll
            for (int mt = 0; mt < 2; mt++) {
                int rb = wm + mt*16 + gr;
                af[mt][0] = Ab[(kk2+gc  )*VAT_AS2_LD + rb    ];
                af[mt][1] = Ab[(kk2+gc  )*VAT_AS2_LD + rb + 8];
                af[mt][2] = Ab[(kk2+gc+4)*VAT_AS2_LD + rb    ];
                af[mt][3] = Ab[(kk2+gc+4)*VAT_AS2_LD + rb + 8];
            }
            #pragma unroll
            for (int nt = 0; nt < 6; nt++) {
                int cb = wn + nt*8 + gr;
                unsigned b0 = Bb2[(kk2+gc  )*VAT_BS2_LD + cb];
                unsigned b1 = Bb2[(kk2+gc+4)*VAT_BS2_LD + cb];
                mma_bf16(acc[0][nt], af[0][0], af[0][1], af[0][2], af[0][3], b0, b1);
                mma_bf16(acc[1][nt], af[1][0], af[1][1], af[1][2], af[1][3], b0, b1);
            }
        }

        if (has_next) {
            int nb = buf ^ 1;
            unsigned* An = As + nb*16*VAT_AS2_LD;
            unsigned* Bn = Bs + nb*16*VAT_BS2_LD;
            float f[8] = {0,0,0,0,0,0,0,0};
            #pragma unroll
            for (int h = 0; h < 4; h++) {
                const __nv_bfloat162* pp2 = (const __nv_bfloat162*)&pa[h];
                float lh = lr[h];
                #pragma unroll
                for (int t = 0; t < 4; t++) {
                    float2 xy = __bfloat1622float2(pp2[t]);
                    f[t*2+0] += lh*xy.x; f[t*2+1] += lh*xy.y;
                }
            }
            #pragma unroll
            for (int jj = 0; jj < 4; jj++)
                An[(app+jj)*VAT_AS2_LD + arow] = pkbf(f[2*jj], f[2*jj+1]);
            #pragma unroll
            for (int t = 0; t < 3; t++) {
                uint4 bv;
                bv.x = pkbf(rb0[t].x, rb1[t].x); bv.y = pkbf(rb0[t].y, rb1[t].y);
                bv.z = pkbf(rb0[t].z, rb1[t].z); bv.w = pkbf(rb0[t].w, rb1[t].w);
                *(uint4*)&Bn[bk[t]*VAT_BS2_LD + bc[t]] = bv;
            }
        }
        __syncthreads();
        buf ^= 1;
    }

    float* vap = va + (size_t)kz*ROWS*192;
    #pragma unroll
    for (int mt = 0; mt < 2; mt++) {
        #pragma unroll
        for (int nt = 0; nt < 6; nt++) {
            int col = wn + nt*8 + gc*2;
            #pragma unroll
            for (int half = 0; half < 2; half++) {
                int m = wm + mt*16 + gr + half*8;
                float2 o;
                o.x = acc[mt][nt][half*2+0];
                o.y = acc[mt][nt][half*2+1];
                *(float2*)(vap + ((size_t)b*Nn + i0 + m)*192 + col) = o;
            }
        }
    }
}

// ---------------- small per-row channel mixes -------------------------------
// vout: sums the KSPLIT vattn partials during load
__global__ void __launch_bounds__(192) vout_kernel(
    const float* __restrict__ vattn, const float* __restrict__ Wvo,
    const float* __restrict__ vin, float* __restrict__ outv)
{
    long long row = blockIdx.x;
    int tid = threadIdx.x;
    __shared__ float vrow[192];
    const size_t ps = (size_t)ROWS*192;
    size_t base = row*192 + tid;
    vrow[tid] = vattn[base] + vattn[base + ps] + vattn[base + 2*ps] + vattn[base + 3*ps];
    __syncthreads();
    int x = tid >> 6, e = tid & 63;
    float acc = 0.f;
    #pragma unroll 8
    for (int c = 0; c < 64; c++) acc += vrow[c*3 + x] * Wvo[c*64 + e];
    outv[row*192 + e*3 + x] = vin[row*192 + e*3 + x] + acc;
}

// 4 rows per CTA, register-blocked weight reuse
__global__ void __launch_bounds__(256) vffn_kernel(
    const float* __restrict__ vn, const float* __restrict__ Wfv1,
    const float* __restrict__ Wfv2, float* __restrict__ outv)
{
    long long row0 = (long long)blockIdx.x * 4;
    int tid = threadIdx.x;
    __shared__ float vrow[4][192];
    __shared__ float t[12][260];

    for (int idx = tid; idx < 768; idx += 256) {
        int r = idx / 192, j = idx - r*192;
        vrow[r][j] = vn[(row0 + r)*192 + j];
    }
    __syncthreads();

    {
        float acc[12];
        #pragma unroll
        for (int j = 0; j < 12; j++) acc[j] = 0.f;
        #pragma unroll 4
        for (int c = 0; c < 64; c++) {
            float w = Wfv1[c*256 + tid];
            #pragma unroll
            for (int r = 0; r < 4; r++)
                #pragma unroll
                for (int x = 0; x < 3; x++)
                    acc[r*3+x] += vrow[r][c*3+x] * w;
        }
        #pragma unroll
        for (int j = 0; j < 12; j++) t[j][tid] = acc[j];
    }
    __syncthreads();

    {
        int c = tid & 63, r = tid >> 6;
        float acc[3] = {0.f, 0.f, 0.f};
        #pragma unroll 4
        for (int h = 0; h < 256; h++) {
            float w2 = Wfv2[h*64 + c];
            #pragma unroll
            for (int x = 0; x < 3; x++)
                acc[x] += t[r*3+x][h] * w2;
        }
        #pragma unroll
        for (int x = 0; x < 3; x++)
            outv[(row0 + r)*192 + c*3 + x] += acc[x];
    }
}

// ---------------- fused attention: tf32 MMA flash, cp.async pipeline ---------
#define ATK 32
#define Q_LD 260
#define K_LD 260
#define V_LD 264
#define PS2_LD 36
#define ATTN_SMEM_FLOATS (64*Q_LD + 2*32*K_LD + 32*V_LD + 4*64*PS2_LD + 256 + 256)

__global__ void __launch_bounds__(256) attn_kernel(
    const float* __restrict__ qg, const float* __restrict__ kg,
    const float* __restrict__ vg, const float* __restrict__ pos,
    const float* __restrict__ wdist, const float* __restrict__ bdist,
    __nv_bfloat16* __restrict__ probsG, float* __restrict__ linvG,
    float* __restrict__ sattn)
{
    extern __shared__ float sm[];
    float* q_s  = sm;
    float* k_s  = q_s + 64*Q_LD;
    float* v_s  = k_s + 2*32*K_LD;
    float* ps   = v_s + 32*V_LD;
    float* posi = ps + 4*64*PS2_LD;
    float* posm = posi + 256;

    const int b  = blockIdx.y;
    const int n0 = blockIdx.x * 64;
    const int tid = threadIdx.x;
    const int lane = tid & 31, wid = tid >> 5;
    const int h  = wid >> 1;
    const int wm = (wid & 1) * 32;
    const int gr = lane >> 2, gc = lane & 3;
    const long long bofs = (long long)b * Nn;

    for (int idx = tid; idx < 4096; idx += 256) {
        int i = idx >> 6, d4 = (idx & 63) << 2;
        float4 qv = *(const float4*)(qg + (bofs + n0 + i)*Ss + d4);
        float* dst = q_s + i*Q_LD + d4;
        dst[0] = f2tff(qv.x); dst[1] = f2tff(qv.y);
        dst[2] = f2tff(qv.z); dst[3] = f2tff(qv.w);
    }
    if (tid < 64) {
        const float* pp = pos + (bofs + n0 + tid)*3;
        float a = pp[0], b2 = pp[1], c = pp[2];
        posi[tid*4+0]=a; posi[tid*4+1]=b2; posi[tid*4+2]=c; posi[tid*4+3]=a*a+b2*b2+c*c;
    }
    const float wh = wdist[h], bh = bdist[h];

    float accO[2][8][4];
    #pragma unroll
    for (int mt = 0; mt < 2; mt++)
        #pragma unroll
        for (int nt = 0; nt < 8; nt++)
            #pragma unroll
            for (int j = 0; j < 4; j++) accO[mt][nt][j] = 0.f;
    float rs[2][2] = {{0.f,0.f},{0.f,0.f}};

    __nv_bfloat16* pgbase = probsG + ((size_t)(b*4 + h)*Nn + n0)*Nn;
    float* psh = ps + h*64*PS2_LD;

    {
        const float* kgp = kg + bofs*Ss;
        for (int idx = tid; idx < 2048; idx += 256) {
            int m = idx >> 6, d4 = (idx & 63) << 2;
            cp16(k_s + m*K_LD + d4, kgp + (long long)m*Ss + d4);
        }
        CP_COMMIT();
        if (tid < 32) {
            const float* pp = pos + (bofs + tid)*3;
            float a = pp[0], b2 = pp[1], c = pp[2];
            posm[tid*4+0]=a; posm[tid*4+1]=b2; posm[tid*4+2]=c; posm[tid*4+3]=a*a+b2*b2+c*c;
        }
    }

    for (int t64 = 0; t64 < 64; t64++) {
        const int m0g = t64 * ATK;
        const int kb = t64 & 1;
        const bool more = (t64 + 1) < 64;

        CP_WAIT0();
        __syncthreads();

        {
            const float* vgp = vg + (bofs + m0g)*(long long)Ss;
            for (int idx = tid; idx < 2048; idx += 256) {
                int m = idx >> 6, d4 = (idx & 63) << 2;
                cp16(v_s + m*V_LD + d4, vgp + (long long)m*Ss + d4);
            }
            CP_COMMIT();
        }
        if (more) {
            const float* kgp = kg + (bofs + m0g + ATK)*(long long)Ss;
            float* kd = k_s + (kb^1)*32*K_LD;
            for (int idx = tid; idx < 2048; idx += 256) {
                int m = idx >> 6, d4 = (idx & 63) << 2;
                cp16(kd + m*K_LD + d4, kgp + (long long)m*Ss + d4);
            }
            CP_COMMIT();
            if (tid < 32) {
                const float* pp = pos + (bofs + m0g + ATK + tid)*3;
                float a = pp[0], b2 = pp[1], c = pp[2];
                float* pm = posm + (kb^1)*128;
                pm[tid*4+0]=a; pm[tid*4+1]=b2; pm[tid*4+2]=c; pm[tid*4+3]=a*a+b2*b2+c*c;
            }
        }

        const float* kbuf = k_s + kb*32*K_LD;
        const float* pmv_buf = posm + kb*128;

        float acc[2][4][4];
        #pragma unroll
        for (int mt = 0; mt < 2; mt++)
            #pragma unroll
            for (int nt = 0; nt < 4; nt++)
                #pragma unroll
                for (int j = 0; j < 4; j++) acc[mt][nt][j] = 0.f;

        #pragma unroll
        for (int kk = 0; kk < 64; kk += 8) {
            unsigned af[2][4];
            #pragma unroll
            for (int mt = 0; mt < 2; mt++) {
                const float* qp = q_s + (wm + mt*16 + gr)*Q_LD + h*64 + kk + gc;
                af[mt][0] = __float_as_uint(qp[0]);
                af[mt][1] = __float_as_uint(qp[8*Q_LD]);
                af[mt][2] = __float_as_uint(qp[4]);
                af[mt][3] = __float_as_uint(qp[8*Q_LD+4]);
            }
            #pragma unroll
            for (int nt = 0; nt < 4; nt++) {
                const float* kp = kbuf + (nt*8 + gr)*K_LD + h*64 + kk + gc;
                unsigned b0 = __float_as_uint(kp[0]);
                unsigned b1 = __float_as_uint(kp[4]);
                mma_tf32(acc[0][nt], af[0][0], af[0][1], af[0][2], af[0][3], b0, b1);
                mma_tf32(acc[1][nt], af[1][0], af[1][1], af[1][2], af[1][3], b0, b1);
            }
        }

        #pragma unroll
        for (int mt = 0; mt < 2; mt++) {
            int r0 = wm + mt*16 + gr;
            float4 pi0 = ((const float4*)posi)[r0];
            float4 pi1 = ((const float4*)posi)[r0+8];
            #pragma unroll
            for (int nt = 0; nt < 4; nt++) {
                int mloc = nt*8 + gc*2;
                float4 pm0 = ((const float4*)pmv_buf)[mloc];
                float4 pm1 = ((const float4*)pmv_buf)[mloc+1];
                float p4[4];
                #pragma unroll
                for (int e = 0; e < 4; e++) {
                    float4 pi = (e < 2) ? pi0 : pi1;
                    float4 pm = (e & 1) ? pm1 : pm0;
                    float d2 = pi.w + pm.w - 2.f*(pi.x*pm.x + pi.y*pm.y + pi.z*pm.z);
                    d2 = fmaxf(d2, 1e-12f);
                    float dist = d2 * rsqrtf(d2);
                    float sx = dist*wh + bh;
                    float sg = __fdividef(1.f, 1.f + __expf(sx));
                    p4[e] = __expf(acc[mt][nt][e]*0.125f) * sg;
                }
                rs[mt][0] += p4[0] + p4[1];
                rs[mt][1] += p4[2] + p4[3];
                *(float2*)(psh + r0*PS2_LD + mloc) = make_float2(f2tff(p4[0]), f2tff(p4[1]));
                *(float2*)(psh + (r0+8)*PS2_LD + mloc) = make_float2(f2tff(p4[2]), f2tff(p4[3]));
                __nv_bfloat162 q01 = __floats2bfloat162_rn(p4[0], p4[1]);
                __nv_bfloat162 q23 = __floats2bfloat162_rn(p4[2], p4[3]);
                __stcs((unsigned int*)(pgbase + (size_t)r0*Nn + m0g + mloc),
                       *(unsigned int*)&q01);
                __stcs((unsigned int*)(pgbase + (size_t)(r0+8)*Nn + m0g + mloc),
                       *(unsigned int*)&q23);
            }
        }

        if (more) { CP_WAIT1(); } else { CP_WAIT0(); }
        __syncthreads();

        #pragma unroll
        for (int kk = 0; kk < 32; kk += 8) {
            unsigned af[2][4];
            #pragma unroll
            for (int mt = 0; mt < 2; mt++) {
                const float* pp = psh + (wm + mt*16 + gr)*PS2_LD + kk + gc;
                af[mt][0] = __float_as_uint(pp[0]);
                af[mt][1] = __float_as_uint(pp[8*PS2_LD]);
                af[mt][2] = __float_as_uint(pp[4]);
                af[mt][3] = __float_as_uint(pp[8*PS2_LD+4]);
            }
            #pragma unroll
            for (int nt = 0; nt < 8; nt++) {
                const float* vp2 = v_s + (kk+gc)*V_LD + h*64 + nt*8 + gr;
                unsigned b0 = __float_as_uint(vp2[0]);
                unsigned b1 = __float_as_uint(vp2[4*V_LD]);
                mma_tf32(accO[0][nt], af[0][0], af[0][1], af[0][2], af[0][3], b0, b1);
                mma_tf32(accO[1][nt], af[1][0], af[1][1], af[1][2], af[1][3], b0, b1);
            }
        }
    }

    float linv[2][2];
    #pragma unroll
    for (int mt = 0; mt < 2; mt++)
        #pragma unroll
        for (int hh = 0; hh < 2; hh++) {
            float v = rs[mt][hh];
            v += __shfl_xor_sync(0xffffffffu, v, 1);
            v += __shfl_xor_sync(0xffffffffu, v, 2);
            linv[mt][hh] = __fdividef(1.f, v);
        }
    if (gc == 0) {
        #pragma unroll
        for (int mt = 0; mt < 2; mt++) {
            int r0 = wm + mt*16 + gr;
            linvG[(size_t)(b*4 + h)*Nn + n0 + r0]     = linv[mt][0];
            linvG[(size_t)(b*4 + h)*Nn + n0 + r0 + 8] = linv[mt][1];
        }
    }
    #pragma unroll
    for (int mt = 0; mt < 2; mt++) {
        #pragma unroll
        for (int nt = 0; nt < 8; nt++) {
            int col = h*64 + nt*8 + gc*2;
            int r0 = wm + mt*16 + gr;
            float2 o0, o1;
            o0.x = accO[mt][nt][0]*linv[mt][0];
            o0.y = accO[mt][nt][1]*linv[mt][0];
            o1.x = accO[mt][nt][2]*linv[mt][1];
            o1.y = accO[mt][nt][3]*linv[mt][1];
            *(float2*)(sattn + (bofs + n0 + r0)*Ss + col) = o0;
            *(float2*)(sattn + (bofs + n0 + r0 + 8)*Ss + col) = o1;
        }
    }
}

// ---------------- launch ------------------------------------------------------
extern "C" void kernel_launch(void* const* d_in, const int* in_sizes, int n_in,
                              void* d_out, int out_size)
{
    const float* s_in  = (const float*)d_in[0];
    const float* v_in  = (const float*)d_in[1];
    const float* pos   = (const float*)d_in[2];
    const float* Wq    = (const float*)d_in[3];
    const float* bq    = (const float*)d_in[4];
    const float* Wk    = (const float*)d_in[5];
    const float* bk    = (const float*)d_in[6];
    const float* Wv    = (const float*)d_in[7];
    const float* bv    = (const float*)d_in[8];
    const float* Wo    = (const float*)d_in[9];
    const float* bo    = (const float*)d_in[10];
    const float* wdist = (const float*)d_in[11];
    const float* bdist = (const float*)d_in[12];
    const float* Wvv   = (const float*)d_in[13];
    const float* Wvo   = (const float*)d_in[14];
    const float* g1    = (const float*)d_in[15];
    const float* be1   = (const float*)d_in[16];
    const float* vs1   = (const float*)d_in[17];
    const float* g2    = (const float*)d_in[18];
    const float* be2   = (const float*)d_in[19];
    const float* vs2   = (const float*)d_in[20];
    const float* Wf1   = (const float*)d_in[21];
    const float* bf1   = (const float*)d_in[22];
    const float* Wf2   = (const float*)d_in[23];
    const float* bf2   = (const float*)d_in[24];
    const float* Wfv1  = (const float*)d_in[25];
    const float* Wfv2  = (const float*)d_in[26];

    float* out_s = (float*)d_out;
    float* out_v = out_s + (size_t)ROWS*Ss;

    void *p_sn, *p_vn, *p_q, *p_k, *p_vp, *p_vmix, *p_pb, *p_li, *p_sa, *p_va, *p_ffn;
    cudaGetSymbolAddress(&p_sn, g_sn);
    cudaGetSymbolAddress(&p_vn, g_vn);
    cudaGetSymbolAddress(&p_q,  g_q);
    cudaGetSymbolAddress(&p_k,  g_k);
    cudaGetSymbolAddress(&p_vp, g_vp);
    cudaGetSymbolAddress(&p_vmix, g_vmix);
    cudaGetSymbolAddress(&p_pb, g_probs);
    cudaGetSymbolAddress(&p_li, g_linv);
    cudaGetSymbolAddress(&p_sa, g_sattn);
    cudaGetSymbolAddress(&p_va, g_vattn);
    cudaGetSymbolAddress(&p_ffn, g_ffn);
    float* sn   = (float*)p_sn;   float* vn   = (float*)p_vn;
    float* q    = (float*)p_q;    float* k    = (float*)p_k;
    float* vp   = (float*)p_vp;   float* vmix = (float*)p_vmix;
    __nv_bfloat16* pb = (__nv_bfloat16*)p_pb;
    float* li   = (float*)p_li;
    float* sa   = (float*)p_sa;   float* va   = (float*)p_va;
    float* ffn  = (float*)p_ffn;

    const int attn_smem = ATTN_SMEM_FLOATS * 4;
    cudaFuncSetAttribute(attn_kernel, cudaFuncAttributeMaxDynamicSharedMemorySize, attn_smem);
    cudaFuncSetAttribute(gemm_tc_kernel, cudaFuncAttributeMaxDynamicSharedMemorySize, GEMM_TC_SMEM);
    cudaFuncSetAttribute(qkv_tc_kernel, cudaFuncAttributeMaxDynamicSharedMemorySize, GEMM_TC_SMEM);
    cudaFuncSetAttribute(vattn_tc_kernel, cudaFuncAttributeMaxDynamicSharedMemorySize, VATTN_SMEM);

    // 1) eq-LN #1 (+ fused vmix = vn @ Wvv)
    eqln_kernel<<<ROWS, 256>>>(s_in, v_in, g1, be1, vs1, sn, vn, Wvv, vmix);

    // 2) QKV projections, single batched launch (bf16 tensor cores)
    qkv_tc_kernel<<<dim3(Ss/64, ROWS/128, 3), 256, GEMM_TC_SMEM>>>(
        sn, Wq, bq, q, Wk, bk, k, Wv, bv, vp);

    // 3) fused single-pass tf32-MMA attention (cp.async pipelined)
    attn_kernel<<<dim3(Nn/64, Bb), 256, attn_smem>>>(q, k, vp, pos, wdist, bdist, pb, li, sa);

    // 4) fused v_attn partials (bf16 MMA, 64-row tiles, 4-way K-split -> 512 CTAs)
    vattn_tc_kernel<<<dim3(Nn/64, Bb, KSPLIT), 256, VATTN_SMEM>>>(pb, li, vmix, va);

    // 5) out_s = s_in + sattn @ Wo + bo
    gemm_tc_kernel<<<dim3(Ss/64, ROWS/128, 1), 256, GEMM_TC_SMEM>>>(sa, Wo, bo, s_in, out_s, ROWS, Ss, Ss, 2);

    // 6) out_v = v_in + (sum of K-split partials) @ Wvo
    vout_kernel<<<ROWS, 192>>>(va, Wvo, v_in, out_v);

    // 7) eq-LN #2 (no vmix)
    eqln_kernel<<<ROWS, 256>>>(out_s, out_v, g2, be2, vs2, sn, vn, nullptr, nullptr);

    // 8) FFN (bf16 tensor cores, GELU + residual epilogues)
    gemm_tc_kernel<<<dim3(Ff/64, ROWS/128, 1), 256, GEMM_TC_SMEM>>>(sn, Wf1, bf1, nullptr, ffn, ROWS, Ff, Ss, 1);
    gemm_tc_kernel<<<dim3(Ss/64, ROWS/128, 1), 256, GEMM_TC_SMEM>>>(ffn, Wf2, bf2, out_s, out_s, ROWS, Ss, Ff, 2);

    // 9) vector FFN (4 rows per CTA)
    vffn_kernel<<<ROWS/4, 256>>>(vn, Wfv1, Wfv2, out_v);
}